// round 16
// baseline (speedup 1.0000x reference)
#include <cuda_runtime.h>
#include <float.h>

#define BN 8
#define NP 2048
#define KNB 40

__device__ __forceinline__ float lrelu(float v) { return v > 0.f ? v : 0.2f * v; }

// ------------------------- scratch (device globals) -------------------------
__device__ __align__(16) float g_xTa[BN * NP * 3];
__device__ __align__(16) float g_xTb[BN * NP * 3];
__device__ __align__(16) float g_xx[BN * NP];
__device__ __align__(16) int   g_idx[BN * NP * KNB];
__device__ __align__(16) float g_t128[BN * NP * 128];
__device__ __align__(16) float g_PQ[BN * NP * 128];
__device__ __align__(16) float g_xC[BN * 64 * NP];
__device__ __align__(16) float g_pm[16 * BN * 1024];
__device__ __align__(16) float g_cat[BN * NP * 192];
__device__ __align__(16) float g_vec[BN * 1088];
__device__ __align__(16) float g_t1024[BN * 1024];
__device__ __align__(16) float g_t512[BN * 512];
__device__ __align__(16) float g_t256[BN * 256];
__device__ __align__(16) float g_T9[BN * 9];
__device__ __align__(16) float g_bias[BN * 256];
__device__ __align__(16) float g_hA[BN * NP * 256];
__device__ __align__(16) float g_hB[BN * NP * 256];

// transposed-weight pool
#define OFF_tc2 0
#define OFF_tc3 (OFF_tc2 + 64*128)
#define OFF_b1b (OFF_tc3 + 128*1024)
#define OFF_b2b (OFF_b1b + 64*64)
#define OFF_m1  (OFF_b2b + 64*64)
#define OFF_h1p (OFF_m1  + 192*1024)
#define OFF_h2  (OFF_h1p + 192*256)
#define OFF_h3  (OFF_h2  + 256*256)
#define OFF_h4  (OFF_h3  + 256*128)
#define OFF_pq2 (OFF_h4  + 128*64)
#define OFF_pq3 (OFF_pq2 + 64*128)
#define WT_TOTAL (OFF_pq3 + 64*128)
__device__ __align__(16) float g_WT[WT_TOTAL];

// ------------------------- prep / small kernels -------------------------
__global__ void tw_kernel(const float* __restrict__ W, int O, int C, int ldW,
                          int coff, float* __restrict__ WT, int OCP) {
    int e = blockIdx.x * blockDim.x + threadIdx.x;
    if (e >= C * OCP) return;
    int c = e / OCP, o = e % OCP;
    WT[e] = (o < O) ? W[(size_t)o * ldW + coff + c] : 0.f;
}

// Batched weight transpose: all remaining segments in ONE launch.
// mode 0: WT[c][o] = (o<O) ? W[o*ldW + coff + c] : 0
// mode 1 (PQ): WT[c][o] = o<64 ? W[o*ldW + c] : W[(o-64)*ldW + C + c] - W[(o-64)*ldW + c]
struct TWTab {
    const float* W[12];
    int C[12], ldW[12], coff[12], OCP[12], O[12], dstOff[12], mode[12], end[12];
    int nseg;
};

__global__ void twall_kernel(TWTab t, float* __restrict__ WT) {
    int e = blockIdx.x * blockDim.x + threadIdx.x;
    int s = 0;
    while (s < t.nseg && e >= t.end[s]) s++;
    if (s >= t.nseg) return;
    int le = e - (s ? t.end[s - 1] : 0);
    int c = le / t.OCP[s], o = le % t.OCP[s];
    float v;
    if (t.mode[s] == 0) {
        v = (o < t.O[s]) ? t.W[s][(size_t)o * t.ldW[s] + t.coff[s] + c] : 0.f;
    } else {
        if (o < 64) v = t.W[s][(size_t)o * t.ldW[s] + c];
        else v = t.W[s][(size_t)(o - 64) * t.ldW[s] + t.C[s] + c]
               - t.W[s][(size_t)(o - 64) * t.ldW[s] + c];
    }
    WT[t.dstOff[s] + le] = v;
}

// prep + pq3 fused: xT, xx, and PQ=[Wa@x | (Wb-Wa)@x] in one pass
__global__ void prep_pq_kernel(const float* __restrict__ x, const float* __restrict__ W,
                               float* __restrict__ xT, float* __restrict__ xx,
                               float* __restrict__ PQ) {
    __shared__ float sw[384];
    int b = blockIdx.y;
    int n = blockIdx.x * blockDim.x + threadIdx.x;
    int tid = threadIdx.x;
    for (int e = tid; e < 384; e += blockDim.x) {
        int o = e / 3, c = e % 3;
        sw[e] = (o < 64) ? W[o * 6 + c] : (W[(o - 64) * 6 + 3 + c] - W[(o - 64) * 6 + c]);
    }
    __syncthreads();
    float v0 = x[((size_t)b * 3 + 0) * NP + n];
    float v1 = x[((size_t)b * 3 + 1) * NP + n];
    float v2 = x[((size_t)b * 3 + 2) * NP + n];
    float* o = &xT[((size_t)b * NP + n) * 3];
    o[0] = v0; o[1] = v1; o[2] = v2;
    xx[b * NP + n] = v0 * v0 + v1 * v1 + v2 * v2;
    float* out = PQ + ((size_t)b * NP + n) * 128;
    for (int oo = 0; oo < 128; oo++)
        out[oo] = sw[oo * 3] * v0 + sw[oo * 3 + 1] * v1 + sw[oo * 3 + 2] * v2;
}

// transform + pq3 fused
__global__ void transform_pq_kernel(const float* __restrict__ x, const float* __restrict__ T9,
                                    const float* __restrict__ W,
                                    float* __restrict__ xT, float* __restrict__ xx,
                                    float* __restrict__ PQ) {
    __shared__ float sw[384];
    int b = blockIdx.y;
    int n = blockIdx.x * blockDim.x + threadIdx.x;
    int tid = threadIdx.x;
    for (int e = tid; e < 384; e += blockDim.x) {
        int o = e / 3, c = e % 3;
        sw[e] = (o < 64) ? W[o * 6 + c] : (W[(o - 64) * 6 + 3 + c] - W[(o - 64) * 6 + c]);
    }
    __syncthreads();
    const float* T = &T9[b * 9];
    float v0 = x[((size_t)b * 3 + 0) * NP + n];
    float v1 = x[((size_t)b * 3 + 1) * NP + n];
    float v2 = x[((size_t)b * 3 + 2) * NP + n];
    float y0 = v0 * T[0] + v1 * T[3] + v2 * T[6];
    float y1 = v0 * T[1] + v1 * T[4] + v2 * T[7];
    float y2 = v0 * T[2] + v1 * T[5] + v2 * T[8];
    float* o = &xT[((size_t)b * NP + n) * 3];
    o[0] = y0; o[1] = y1; o[2] = y2;
    xx[b * NP + n] = y0 * y0 + y1 * y1 + y2 * y2;
    float* out = PQ + ((size_t)b * NP + n) * 128;
    for (int oo = 0; oo < 128; oo++)
        out[oo] = sw[oo * 3] * y0 + sw[oo * 3 + 1] * y1 + sw[oo * 3 + 2] * y2;
}

// ------------------------- kNN selection (REDUX argmax + top-4 cache) -------
__device__ __forceinline__ unsigned f2u(float f) {
    unsigned u = __float_as_uint(f);
    return (f >= 0.f) ? (u | 0x80000000u) : ~u;
}

struct Top4 { float v0, v1, v2, v3; int i0, i1, i2, i3; };

__device__ __forceinline__ void lane_top4(const float* dr, int lane, Top4& t) {
    t.v0 = t.v1 = t.v2 = t.v3 = -FLT_MAX;
    t.i0 = t.i1 = t.i2 = t.i3 = 0x7fffffff;
#pragma unroll 4
    for (int s = 0; s < NP / 32; s++) {
        int j = lane + (s << 5);
        float val = dr[j];
        if (val > t.v3) {
            if (val > t.v2) {
                if (val > t.v1) {
                    if (val > t.v0) {
                        t.v3 = t.v2; t.i3 = t.i2; t.v2 = t.v1; t.i2 = t.i1;
                        t.v1 = t.v0; t.i1 = t.i0; t.v0 = val; t.i0 = j;
                    } else {
                        t.v3 = t.v2; t.i3 = t.i2; t.v2 = t.v1; t.i2 = t.i1;
                        t.v1 = val; t.i1 = j;
                    }
                } else { t.v3 = t.v2; t.i3 = t.i2; t.v2 = val; t.i2 = j; }
            } else { t.v3 = val; t.i3 = j; }
        }
    }
}

__device__ __forceinline__ void knn_select(float* dr, int* orow, int lane) {
    Top4 t;
    lane_top4(dr, lane, t);
    unsigned key = f2u(t.v0);
    for (int k = 0; k < KNB; k++) {
        unsigned bk = __reduce_max_sync(~0u, key);
        unsigned winners = __ballot_sync(~0u, key == bk);
        int wl = __ffs(winners) - 1;
        int bi = __shfl_sync(~0u, t.i0, wl);
        if (lane == 0) orow[k] = bi;
        if (lane == wl) {
            dr[t.i0] = -FLT_MAX;
            t.v0 = t.v1; t.i0 = t.i1;
            t.v1 = t.v2; t.i1 = t.i2;
            t.v2 = t.v3; t.i2 = t.i3;
            t.v3 = -FLT_MAX; t.i3 = 0x7fffffff;
            if (t.v0 == -FLT_MAX) lane_top4(dr, lane, t);
            key = f2u(t.v0);
        }
    }
}

__global__ void knn3_kernel(const float* __restrict__ xT, const float* __restrict__ xx,
                            int* __restrict__ idx) {
    extern __shared__ float dist[];  // 8 * NP
    __shared__ float sctr[8][3];
    const int b = blockIdx.y, r0 = blockIdx.x * 8, tid = threadIdx.x;

    for (int e = tid; e < 24; e += 256)
        sctr[e / 3][e % 3] = xT[((size_t)b * NP + r0 + e / 3) * 3 + e % 3];
    __syncthreads();

    for (int j = tid; j < NP; j += 256) {
        const float* pj = xT + ((size_t)b * NP + j) * 3;
        float w0 = pj[0], w1 = pj[1], w2 = pj[2];
        float xxj = xx[b * NP + j];
#pragma unroll
        for (int r = 0; r < 8; r++) {
            float a = w0 * sctr[r][0] + w1 * sctr[r][1] + w2 * sctr[r][2];
            dist[r * NP + j] = 2.f * a - xxj;
        }
    }
    __syncthreads();

    const int w = tid >> 5, lane = tid & 31;
    knn_select(dist + w * NP, idx + ((size_t)b * NP + r0 + w) * KNB, lane);
}

// C=64 kNN: 8 rows/block, 256 threads, j-vectorized (float4) distance phase
__global__ void knnC_kernel(const float* __restrict__ xC, int* __restrict__ idx) {
    extern __shared__ float dist[];  // 8 * NP
    __shared__ float sctr[8][64];
    const int b = blockIdx.y, r0 = blockIdx.x * 8, tid = threadIdx.x;

    for (int e = tid; e < 8 * 64; e += 256) {
        int r = e / 64, c = e % 64;
        sctr[r][c] = xC[((size_t)b * 64 + c) * NP + r0 + r];
    }
    __syncthreads();

    for (int j4 = tid * 4; j4 < NP; j4 += 1024) {
        float4 acc[8];
#pragma unroll
        for (int r = 0; r < 8; r++) acc[r] = make_float4(0.f, 0.f, 0.f, 0.f);
        float4 sq = make_float4(0.f, 0.f, 0.f, 0.f);
        for (int c = 0; c < 64; c++) {
            float4 v = *(const float4*)&xC[((size_t)b * 64 + c) * NP + j4];
            sq.x += v.x * v.x; sq.y += v.y * v.y; sq.z += v.z * v.z; sq.w += v.w * v.w;
#pragma unroll
            for (int r = 0; r < 8; r++) {
                float s = sctr[r][c];
                acc[r].x += v.x * s; acc[r].y += v.y * s;
                acc[r].z += v.z * s; acc[r].w += v.w * s;
            }
        }
#pragma unroll
        for (int r = 0; r < 8; r++) {
            float4 dv;
            dv.x = 2.f * acc[r].x - sq.x;
            dv.y = 2.f * acc[r].y - sq.y;
            dv.z = 2.f * acc[r].z - sq.z;
            dv.w = 2.f * acc[r].w - sq.w;
            *(float4*)&dist[r * NP + j4] = dv;
        }
    }
    __syncthreads();

    const int w = tid >> 5, lane = tid & 31;
    knn_select(dist + w * NP, idx + ((size_t)b * NP + r0 + w) * KNB, lane);
}

// --------- edge layer-2 (unified: transposed sH, 8x4 tiles, f4 A+W) ---------
// h[k] = lrelu(P[idx[k]] + Q[n]); out = max_k lrelu(h @ W2)
// COUT=128: kt fast within warp (W-load 1 wf); COUT=64: ot fast (A-load 1 wf).
template <int COUT, int P>
__global__ __launch_bounds__(320) void edge2_kernel(
        const float* __restrict__ PQ, const int* __restrict__ idx,
        const float* __restrict__ W2T,  // [64][COUT]
        float* __restrict__ out, int old, int ooff, float* __restrict__ outC) {
    constexpr int NT = 320;
    constexpr int KT = KNB / 8;           // 5
    constexpr int OT = COUT / 4;
    constexpr int TPP = KT * OT;
    static_assert(P * TPP == NT, "tile/thread mismatch");
    constexpr int PK = P * KNB;           // 80 or 160 (multiple of 4)
    extern __shared__ float sm[];
    float* sW2 = sm;                      // 64*COUT
    float* sHT = sW2 + 64 * COUT;         // [64][PK]  (c-major, k contiguous)
    float* sP  = sHT + 64 * PK;           // P*KT*COUT partial maxes
    __shared__ float sQ[P][64];
    __shared__ int sidx[P * KNB];

    const int b = blockIdx.y, n0 = blockIdx.x * P, tid = threadIdx.x;

    for (int e = tid; e < 64 * COUT; e += NT) sW2[e] = W2T[e];
    for (int e = tid; e < P * KNB; e += NT)
        sidx[e] = idx[((size_t)b * NP + n0 + e / KNB) * KNB + e % KNB];
    for (int e = tid; e < P * 64; e += NT)
        sQ[e >> 6][e & 63] = PQ[((size_t)b * NP + n0 + (e >> 6)) * 128 + 64 + (e & 63)];
    __syncthreads();

    // gather + transpose
    for (int e = tid; e < PK * 16; e += NT) {
        int pk = e % PK, c4 = e / PK;
        int p = pk / KNB;
        float4 v = *(const float4*)(PQ + ((size_t)b * NP + sidx[pk]) * 128 + c4 * 4);
        const float* q = &sQ[p][c4 * 4];
        sHT[(c4 * 4 + 0) * PK + pk] = lrelu(v.x + q[0]);
        sHT[(c4 * 4 + 1) * PK + pk] = lrelu(v.y + q[1]);
        sHT[(c4 * 4 + 2) * PK + pk] = lrelu(v.z + q[2]);
        sHT[(c4 * 4 + 3) * PK + pk] = lrelu(v.w + q[3]);
    }
    __syncthreads();

    {
        int p = tid / TPP, r = tid % TPP;
        int kt, ot;
        if (COUT == 128) { kt = r % KT; ot = r / KT; }
        else             { kt = r / OT; ot = r % OT; }
        const float* Abase = sHT + p * KNB + kt * 8;   // + c*PK per step
        const float* W = sW2 + ot * 4;
        float acc[8][4] = {};
        for (int c = 0; c < 64; c++) {
            float4 A0 = *(const float4*)(Abase + c * PK);
            float4 A1 = *(const float4*)(Abase + c * PK + 4);
            float4 w = *(const float4*)(W + c * COUT);
            float a[8] = {A0.x, A0.y, A0.z, A0.w, A1.x, A1.y, A1.z, A1.w};
#pragma unroll
            for (int i = 0; i < 8; i++) {
                acc[i][0] += a[i] * w.x; acc[i][1] += a[i] * w.y;
                acc[i][2] += a[i] * w.z; acc[i][3] += a[i] * w.w;
            }
        }
        // fused max over the 8 k-rows of this tile
        float* d = sP + ((size_t)p * KT + kt) * COUT + ot * 4;
#pragma unroll
        for (int oi = 0; oi < 4; oi++) {
            float m = lrelu(acc[0][oi]);
#pragma unroll
            for (int i = 1; i < 8; i++) m = fmaxf(m, lrelu(acc[i][oi]));
            d[oi] = m;
        }
    }
    __syncthreads();

    for (int o = tid; o < P * COUT; o += NT) {
        int p = o / COUT, oo = o % COUT;
        const float* col = sP + (size_t)p * KT * COUT + oo;
        float m = col[0];
#pragma unroll
        for (int kt = 1; kt < KT; kt++) m = fmaxf(m, col[kt * COUT]);
        int n = n0 + p;
        out[((size_t)b * NP + n) * old + ooff + oo] = m;
        if (outC) outC[((size_t)b * 64 + oo) * NP + n] = m;
    }
}

// E4: out[n,o] = lrelu(max_k P[idx[n,k],o] + Q[n,o])
__global__ void gathermax_kernel(const float* __restrict__ PQ, const int* __restrict__ idx,
                                 float* __restrict__ out, int old, int ooff) {
    __shared__ int sidx[2][KNB];
    int b = blockIdx.y, tid = threadIdx.x;
    int p = tid >> 6, oo = tid & 63;
    int n = blockIdx.x * 2 + p;
    if (tid < 2 * KNB)
        sidx[tid / KNB][tid % KNB] = idx[((size_t)b * NP + blockIdx.x * 2 + tid / KNB) * KNB + tid % KNB];
    __syncthreads();
    float m = -FLT_MAX;
#pragma unroll 4
    for (int k = 0; k < KNB; k++)
        m = fmaxf(m, PQ[((size_t)b * NP + sidx[p][k]) * 128 + oo]);
    float q = PQ[((size_t)b * NP + n) * 128 + 64 + oo];
    out[((size_t)b * NP + n) * old + ooff + oo] = lrelu(m + q);
}

// ------------------------- 128x128-tile pointwise conv (8x8 microtile) ------
__global__ __launch_bounds__(256) void pconv128_kernel(
        const float* __restrict__ in, int ld, int coff,
        const float* __restrict__ WT, int CIN, int OCP,
        const float* __restrict__ bias, int bstride,
        float* __restrict__ out, int old, int ooff, int act,
        float* __restrict__ pmax) {
    __shared__ float sA[16][132];
    __shared__ float sB[16][128];
    __shared__ float sR[16][128];
    const int b = blockIdx.z;
    const int n0 = blockIdx.x * 128, o0 = blockIdx.y * 128;
    const int tid = threadIdx.x;
    const int tx = tid & 15, ty = tid >> 4;
    float acc[8][8] = {};

    for (int c0 = 0; c0 < CIN; c0 += 16) {
        {
            int n = tid >> 1;
            int cbase = (tid & 1) * 4;
            const float* src = in + ((size_t)b * NP + n0 + n) * ld + coff + c0;
#pragma unroll
            for (int p = 0; p < 2; p++) {
                float4 v = *(const float4*)(src + cbase + p * 8);
                sA[cbase + p * 8 + 0][n] = v.x; sA[cbase + p * 8 + 1][n] = v.y;
                sA[cbase + p * 8 + 2][n] = v.z; sA[cbase + p * 8 + 3][n] = v.w;
            }
        }
        {
            int c = tid >> 5, o4 = (tid & 31) * 4;
#pragma unroll
            for (int p = 0; p < 2; p++)
                *(float4*)&sB[c + p * 8][o4] =
                    *(const float4*)(WT + (size_t)(c0 + c + p * 8) * OCP + o0 + o4);
        }
        __syncthreads();
#pragma unroll
        for (int c = 0; c < 16; c++) {
            float4 a0 = *(const float4*)&sA[c][ty * 8];
            float4 a1 = *(const float4*)&sA[c][ty * 8 + 4];
            float4 b0 = *(const float4*)&sB[c][tx * 8];
            float4 b1 = *(const float4*)&sB[c][tx * 8 + 4];
            float av[8] = {a0.x, a0.y, a0.z, a0.w, a1.x, a1.y, a1.z, a1.w};
            float bv[8] = {b0.x, b0.y, b0.z, b0.w, b1.x, b1.y, b1.z, b1.w};
#pragma unroll
            for (int i = 0; i < 8; i++)
#pragma unroll
                for (int j = 0; j < 8; j++) acc[i][j] += av[i] * bv[j];
        }
        __syncthreads();
    }

    if (pmax) {  // act=1 assumed; per-block partial max over 128 n's
#pragma unroll
        for (int j = 0; j < 8; j++) {
            float m = lrelu(acc[0][j]);
#pragma unroll
            for (int i = 1; i < 8; i++) m = fmaxf(m, lrelu(acc[i][j]));
            sR[ty][tx * 8 + j] = m;
        }
        __syncthreads();
        if (tid < 128) {
            float m = sR[0][tid];
#pragma unroll
            for (int r = 1; r < 16; r++) m = fmaxf(m, sR[r][tid]);
            pmax[((size_t)blockIdx.x * BN + b) * 1024 + o0 + tid] = m;
        }
        return;
    }

    float bvv[8];
    if (bias) {
#pragma unroll
        for (int j = 0; j < 8; j++) bvv[j] = bias[b * bstride + o0 + tx * 8 + j];
    }
#pragma unroll
    for (int i = 0; i < 8; i++) {
        int n = n0 + ty * 8 + i;
        float vals[8];
#pragma unroll
        for (int j = 0; j < 8; j++) {
            float v = acc[i][j];
            if (bias) v += bvv[j];
            if (act) v = lrelu(v);
            vals[j] = v;
        }
        float* dst = out + ((size_t)b * NP + n) * old + ooff + o0 + tx * 8;
        *(float4*)dst = make_float4(vals[0], vals[1], vals[2], vals[3]);
        *(float4*)(dst + 4) = make_float4(vals[4], vals[5], vals[6], vals[7]);
    }
}

// ------------------------- small-OC pointwise conv (final layer) ------------
__global__ void pconv_kernel(const float* __restrict__ in, int ld, int coff,
                             const float* __restrict__ WT, int CIN, int OCP,
                             float* __restrict__ out, int OC) {
    __shared__ float sA[16][68];
    __shared__ float sB[16][64];
    const int b = blockIdx.z;
    const int n0 = blockIdx.x * 64, o0 = blockIdx.y * 64;
    const int tid = threadIdx.x;
    const int tx = tid % 16, ty = tid / 16;
    float acc[4][4] = {};

    for (int c0 = 0; c0 < CIN; c0 += 16) {
        {
            int p = tid >> 2, c4 = (tid & 3) * 4;
            const float* src = in + ((size_t)b * NP + n0 + p) * ld + coff + c0 + c4;
            float4 v = *(const float4*)src;
            sA[c4 + 0][p] = v.x; sA[c4 + 1][p] = v.y;
            sA[c4 + 2][p] = v.z; sA[c4 + 3][p] = v.w;
        }
        {
            int c = tid >> 4, o4 = (tid & 15) * 4;
            *(float4*)&sB[c][o4] = *(const float4*)(WT + (size_t)(c0 + c) * OCP + o0 + o4);
        }
        __syncthreads();
#pragma unroll
        for (int c = 0; c < 16; c++) {
            float4 av = *(const float4*)&sA[c][ty * 4];
            float4 bv = *(const float4*)&sB[c][tx * 4];
            acc[0][0]+=av.x*bv.x; acc[0][1]+=av.x*bv.y; acc[0][2]+=av.x*bv.z; acc[0][3]+=av.x*bv.w;
            acc[1][0]+=av.y*bv.x; acc[1][1]+=av.y*bv.y; acc[1][2]+=av.y*bv.z; acc[1][3]+=av.y*bv.w;
            acc[2][0]+=av.z*bv.x; acc[2][1]+=av.z*bv.y; acc[2][2]+=av.z*bv.z; acc[2][3]+=av.z*bv.w;
            acc[3][0]+=av.w*bv.x; acc[3][1]+=av.w*bv.y; acc[3][2]+=av.w*bv.z; acc[3][3]+=av.w*bv.w;
        }
        __syncthreads();
    }

#pragma unroll
    for (int i = 0; i < 4; i++) {
        int n = n0 + ty * 4 + i;
#pragma unroll
        for (int j = 0; j < 4; j++) {
            int o = o0 + tx * 4 + j;
            if (o >= OC) continue;
            out[((size_t)b * OC + o) * NP + n] = acc[i][j];  // column-major final output
        }
    }
}

__global__ void pmaxreduce_kernel(const float* __restrict__ pm, float* __restrict__ out,
                                  int ostride, int ooff, int nblk) {
    int gid = blockIdx.x * blockDim.x + threadIdx.x;
    if (gid >= BN * 1024) return;
    int b = gid / 1024, o = gid % 1024;
    float m = -FLT_MAX;
    for (int blk = 0; blk < nblk; blk++)
        m = fmaxf(m, pm[((size_t)blk * BN + b) * 1024 + o]);
    out[(size_t)b * ostride + ooff + o] = m;
}

__global__ void fc_kernel(const float* __restrict__ in, int istride, int C,
                          const float* __restrict__ W, int wld, int O,
                          const float* __restrict__ bias, int bstride,
                          float* __restrict__ out, int ostride, int ooff, int act) {
    int b = blockIdx.x;
    int o = blockIdx.y * blockDim.x + threadIdx.x;
    if (o >= O) return;
    const float* ip = in + (size_t)b * istride;
    const float* wp = W + (size_t)o * wld;
    float s = 0.f;
    for (int c = 0; c < C; c++) s += ip[c] * wp[c];
    if (bias) s += bias[(size_t)b * bstride + o];
    if (act) s = lrelu(s);
    out[(size_t)b * ostride + ooff + o] = s;
}

// ------------------------- host -------------------------
extern "C" void kernel_launch(void* const* d_in, const int* in_sizes, int n_in,
                              void* d_out, int out_size) {
    const float* x    = (const float*)d_in[0];
    const float* l    = (const float*)d_in[1];
    const float* t_c1 = (const float*)d_in[2];
    const float* t_c2 = (const float*)d_in[3];
    const float* t_c3 = (const float*)d_in[4];
    const float* t_f1 = (const float*)d_in[5];
    const float* t_f2 = (const float*)d_in[6];
    const float* t_f3w= (const float*)d_in[7];
    const float* t_f3b= (const float*)d_in[8];
    const float* b1a  = (const float*)d_in[9];
    const float* b1b  = (const float*)d_in[10];
    const float* b2a  = (const float*)d_in[11];
    const float* b2b  = (const float*)d_in[12];
    const float* b3a  = (const float*)d_in[13];
    const float* m1   = (const float*)d_in[14];
    const float* m2   = (const float*)d_in[15];
    const float* h1   = (const float*)d_in[16];
    const float* h2   = (const float*)d_in[17];
    const float* h3   = (const float*)d_in[18];
    const float* h4   = (const float*)d_in[19];

    float *xTa, *xTb, *xx, *t128, *PQ, *xC, *pm, *cat, *vec, *t1024, *t512, *t256, *T9, *bsb, *hA, *hB, *WT;
    int* idxp;
    cudaGetSymbolAddress((void**)&xTa, g_xTa);
    cudaGetSymbolAddress((void**)&xTb, g_xTb);
    cudaGetSymbolAddress((void**)&xx, g_xx);
    cudaGetSymbolAddress((void**)&idxp, g_idx);
    cudaGetSymbolAddress((void**)&t128, g_t128);
    cudaGetSymbolAddress((void**)&PQ, g_PQ);
    cudaGetSymbolAddress((void**)&xC, g_xC);
    cudaGetSymbolAddress((void**)&pm, g_pm);
    cudaGetSymbolAddress((void**)&cat, g_cat);
    cudaGetSymbolAddress((void**)&vec, g_vec);
    cudaGetSymbolAddress((void**)&t1024, g_t1024);
    cudaGetSymbolAddress((void**)&t512, g_t512);
    cudaGetSymbolAddress((void**)&t256, g_t256);
    cudaGetSymbolAddress((void**)&T9, g_T9);
    cudaGetSymbolAddress((void**)&bsb, g_bias);
    cudaGetSymbolAddress((void**)&hA, g_hA);
    cudaGetSymbolAddress((void**)&hB, g_hB);
    cudaGetSymbolAddress((void**)&WT, g_WT);

    const int KNN_SMEM = 8 * NP * 4;                                    // 65536
    const int E128 = (64*128 + 64*(2*KNB) + 2*(KNB/8)*128) * 4;         // 58368
    const int E64  = (64*64  + 64*(4*KNB) + 4*(KNB/8)*64) * 4;          // 62464
    cudaFuncSetAttribute(knn3_kernel, cudaFuncAttributeMaxDynamicSharedMemorySize, KNN_SMEM);
    cudaFuncSetAttribute(knnC_kernel, cudaFuncAttributeMaxDynamicSharedMemorySize, KNN_SMEM);
    cudaFuncSetAttribute((const void*)edge2_kernel<128,2>, cudaFuncAttributeMaxDynamicSharedMemorySize, E128);
    cudaFuncSetAttribute((const void*)edge2_kernel<64,4>,  cudaFuncAttributeMaxDynamicSharedMemorySize, E64);

    // ---- front ordered so launch index 3 (profiled) = edge2<128,2> ----
    prep_pq_kernel<<<dim3(NP / 256, BN), 256>>>(x, t_c1, xTa, xx, PQ);                  // 0
    tw_kernel<<<(64*128 + 255) / 256, 256>>>(t_c2, 128, 64, 64, 0, WT + OFF_tc2, 128);  // 1
    knn3_kernel<<<dim3(NP / 8, BN), 256, KNN_SMEM>>>(xTa, xx, idxp);                    // 2
    edge2_kernel<128,2><<<dim3(NP / 2, BN), 320, E128>>>(PQ, idxp, WT + OFF_tc2,
                                                         t128, 128, 0, nullptr);        // 3 (profiled)

    // ---- remaining weight prep: ONE batched launch ----
    {
        TWTab t = {};
        struct S { const float* W; int C, ldW, coff, OCP, O, dstOff, mode; };
        S segs[] = {
            {t_c3, 128, 128, 0, 1024, 1024, OFF_tc3, 0},
            {b1b, 64, 64, 0, 64, 64, OFF_b1b, 0},
            {b2b, 64, 64, 0, 64, 64, OFF_b2b, 0},
            {m1, 192, 192, 0, 1024, 1024, OFF_m1, 0},
            {h1, 192, 1280, 1088, 256, 256, OFF_h1p, 0},
            {h2, 256, 256, 0, 256, 256, OFF_h2, 0},
            {h3, 256, 256, 0, 128, 128, OFF_h3, 0},
            {h4, 128, 128, 0, 64, 50, OFF_h4, 0},
            {b2a, 64, 128, 0, 128, 0, OFF_pq2, 1},
            {b3a, 64, 128, 0, 128, 0, OFF_pq3, 1},
        };
        int acc = 0;
        t.nseg = 10;
        for (int s = 0; s < 10; s++) {
            t.W[s] = segs[s].W; t.C[s] = segs[s].C; t.ldW[s] = segs[s].ldW;
            t.coff[s] = segs[s].coff; t.OCP[s] = segs[s].OCP; t.O[s] = segs[s].O;
            t.dstOff[s] = segs[s].dstOff; t.mode[s] = segs[s].mode;
            acc += segs[s].C * segs[s].OCP;
            t.end[s] = acc;
        }
        twall_kernel<<<(acc + 255) / 256, 256>>>(t, WT);
    }

    // ---- transform net (cont.) ----
    pconv128_kernel<<<dim3(16, 8, BN), 256>>>(t128, 128, 0, WT + OFF_tc3, 128, 1024,
                                              nullptr, 0, nullptr, 0, 0, 1, pm);
    pmaxreduce_kernel<<<(BN * 1024 + 255) / 256, 256>>>(pm, t1024, 1024, 0, 16);
    fc_kernel<<<dim3(BN, 2), 256>>>(t1024, 1024, 1024, t_f1, 1024, 512, nullptr, 0, t512, 512, 0, 1);
    fc_kernel<<<dim3(BN, 1), 256>>>(t512, 512, 512, t_f2, 512, 256, nullptr, 0, t256, 256, 0, 1);
    fc_kernel<<<dim3(BN, 1), 256>>>(t256, 256, 256, t_f3w, 256, 9, t_f3b, 0, T9, 9, 0, 0);
    transform_pq_kernel<<<dim3(NP / 256, BN), 256>>>(x, T9, b1a, xTb, xx, PQ);

    // ---- edge block 1 ----
    knn3_kernel<<<dim3(NP / 8, BN), 256, KNN_SMEM>>>(xTb, xx, idxp);
    edge2_kernel<64,4><<<dim3(NP / 4, BN), 320, E64>>>(PQ, idxp, WT + OFF_b1b, cat, 192, 0, xC);

    // ---- edge block 2 ----
    knnC_kernel<<<dim3(NP / 8, BN), 256, KNN_SMEM>>>(xC, idxp);
    pconv128_kernel<<<dim3(16, 1, BN), 256>>>(cat, 192, 0, WT + OFF_pq2, 64, 128,
                                              nullptr, 0, PQ, 128, 0, 0, nullptr);
    edge2_kernel<64,4><<<dim3(NP / 4, BN), 320, E64>>>(PQ, idxp, WT + OFF_b2b, cat, 192, 64, xC);

    // ---- edge block 3 (collapsed) ----
    knnC_kernel<<<dim3(NP / 8, BN), 256, KNN_SMEM>>>(xC, idxp);
    pconv128_kernel<<<dim3(16, 1, BN), 256>>>(cat, 192, 64, WT + OFF_pq3, 64, 128,
                                              nullptr, 0, PQ, 128, 0, 0, nullptr);
    gathermax_kernel<<<dim3(NP / 2, BN), 128>>>(PQ, idxp, cat, 192, 128);

    // ---- global features ----
    pconv128_kernel<<<dim3(16, 8, BN), 256>>>(cat, 192, 0, WT + OFF_m1, 192, 1024,
                                              nullptr, 0, nullptr, 0, 0, 1, pm);
    pmaxreduce_kernel<<<(BN * 1024 + 255) / 256, 256>>>(pm, vec, 1088, 0, 16);
    fc_kernel<<<dim3(BN, 1), 256>>>(l, 16, 16, m2, 16, 64, nullptr, 0, vec, 1088, 1024, 1);
    fc_kernel<<<dim3(BN, 1), 256>>>(vec, 1088, 1088, h1, 1280, 256, nullptr, 0, bsb, 256, 0, 0);

    // ---- head ----
    pconv128_kernel<<<dim3(16, 2, BN), 256>>>(cat, 192, 0, WT + OFF_h1p, 192, 256,
                                              bsb, 256, hA, 256, 0, 1, nullptr);
    pconv128_kernel<<<dim3(16, 2, BN), 256>>>(hA, 256, 0, WT + OFF_h2, 256, 256,
                                              nullptr, 0, hB, 256, 0, 1, nullptr);
    pconv128_kernel<<<dim3(16, 1, BN), 256>>>(hB, 256, 0, WT + OFF_h3, 256, 128,
                                              nullptr, 0, hA, 128, 0, 1, nullptr);
    pconv_kernel<<<dim3(32, 1, BN), 256>>>(hA, 128, 0, WT + OFF_h4, 128, 64,
                                           (float*)d_out, 50);
}

// round 17
// speedup vs baseline: 1.0582x; 1.0582x over previous
#include <cuda_runtime.h>
#include <float.h>

#define BN 8
#define NP 2048
#define KNB 40

__device__ __forceinline__ float lrelu(float v) { return v > 0.f ? v : 0.2f * v; }

// ------------------------- scratch (device globals) -------------------------
__device__ __align__(16) float g_xTa[BN * NP * 3];
__device__ __align__(16) float g_xTb[BN * NP * 3];
__device__ __align__(16) float g_xx[BN * NP];
__device__ __align__(16) int   g_idx[BN * NP * KNB];
__device__ __align__(16) float g_t128[BN * NP * 128];
__device__ __align__(16) float g_PQ[BN * NP * 128];
__device__ __align__(16) float g_xC[BN * 64 * NP];
__device__ __align__(16) float g_pm[16 * BN * 1024];
__device__ __align__(16) float g_cat[BN * NP * 192];
__device__ __align__(16) float g_vec[BN * 1088];
__device__ __align__(16) float g_t1024[BN * 1024];
__device__ __align__(16) float g_t512[BN * 512];
__device__ __align__(16) float g_t256[BN * 256];
__device__ __align__(16) float g_T9[BN * 9];
__device__ __align__(16) float g_bias[BN * 256];
__device__ __align__(16) float g_hA[BN * NP * 256];
__device__ __align__(16) float g_hB[BN * NP * 256];

// transposed-weight pool
#define OFF_tc2 0
#define OFF_tc3 (OFF_tc2 + 64*128)
#define OFF_b1b (OFF_tc3 + 128*1024)
#define OFF_b2b (OFF_b1b + 64*64)
#define OFF_m1  (OFF_b2b + 64*64)
#define OFF_h1p (OFF_m1  + 192*1024)
#define OFF_h2  (OFF_h1p + 192*256)
#define OFF_h3  (OFF_h2  + 256*256)
#define OFF_h4  (OFF_h3  + 256*128)
#define OFF_pq2 (OFF_h4  + 128*64)
#define OFF_pq3 (OFF_pq2 + 64*128)
#define WT_TOTAL (OFF_pq3 + 64*128)
__device__ __align__(16) float g_WT[WT_TOTAL];

// ------------------------- prep / small kernels -------------------------
__global__ void tw_kernel(const float* __restrict__ W, int O, int C, int ldW,
                          int coff, float* __restrict__ WT, int OCP) {
    int e = blockIdx.x * blockDim.x + threadIdx.x;
    if (e >= C * OCP) return;
    int c = e / OCP, o = e % OCP;
    WT[e] = (o < O) ? W[(size_t)o * ldW + coff + c] : 0.f;
}

// Batched weight transpose: all remaining segments in ONE launch.
struct TWTab {
    const float* W[12];
    int C[12], ldW[12], coff[12], OCP[12], O[12], dstOff[12], mode[12], end[12];
    int nseg;
};

__global__ void twall_kernel(TWTab t, float* __restrict__ WT) {
    int e = blockIdx.x * blockDim.x + threadIdx.x;
    int s = 0;
    while (s < t.nseg && e >= t.end[s]) s++;
    if (s >= t.nseg) return;
    int le = e - (s ? t.end[s - 1] : 0);
    int c = le / t.OCP[s], o = le % t.OCP[s];
    float v;
    if (t.mode[s] == 0) {
        v = (o < t.O[s]) ? t.W[s][(size_t)o * t.ldW[s] + t.coff[s] + c] : 0.f;
    } else {
        if (o < 64) v = t.W[s][(size_t)o * t.ldW[s] + c];
        else v = t.W[s][(size_t)(o - 64) * t.ldW[s] + t.C[s] + c]
               - t.W[s][(size_t)(o - 64) * t.ldW[s] + c];
    }
    WT[t.dstOff[s] + le] = v;
}

// prep + pq3 fused: xT, xx, and PQ=[Wa@x | (Wb-Wa)@x] in one pass
__global__ void prep_pq_kernel(const float* __restrict__ x, const float* __restrict__ W,
                               float* __restrict__ xT, float* __restrict__ xx,
                               float* __restrict__ PQ) {
    __shared__ float sw[384];
    int b = blockIdx.y;
    int n = blockIdx.x * blockDim.x + threadIdx.x;
    int tid = threadIdx.x;
    for (int e = tid; e < 384; e += blockDim.x) {
        int o = e / 3, c = e % 3;
        sw[e] = (o < 64) ? W[o * 6 + c] : (W[(o - 64) * 6 + 3 + c] - W[(o - 64) * 6 + c]);
    }
    __syncthreads();
    float v0 = x[((size_t)b * 3 + 0) * NP + n];
    float v1 = x[((size_t)b * 3 + 1) * NP + n];
    float v2 = x[((size_t)b * 3 + 2) * NP + n];
    float* o = &xT[((size_t)b * NP + n) * 3];
    o[0] = v0; o[1] = v1; o[2] = v2;
    xx[b * NP + n] = v0 * v0 + v1 * v1 + v2 * v2;
    float* out = PQ + ((size_t)b * NP + n) * 128;
    for (int oo = 0; oo < 128; oo++)
        out[oo] = sw[oo * 3] * v0 + sw[oo * 3 + 1] * v1 + sw[oo * 3 + 2] * v2;
}

// transform + pq3 fused
__global__ void transform_pq_kernel(const float* __restrict__ x, const float* __restrict__ T9,
                                    const float* __restrict__ W,
                                    float* __restrict__ xT, float* __restrict__ xx,
                                    float* __restrict__ PQ) {
    __shared__ float sw[384];
    int b = blockIdx.y;
    int n = blockIdx.x * blockDim.x + threadIdx.x;
    int tid = threadIdx.x;
    for (int e = tid; e < 384; e += blockDim.x) {
        int o = e / 3, c = e % 3;
        sw[e] = (o < 64) ? W[o * 6 + c] : (W[(o - 64) * 6 + 3 + c] - W[(o - 64) * 6 + c]);
    }
    __syncthreads();
    const float* T = &T9[b * 9];
    float v0 = x[((size_t)b * 3 + 0) * NP + n];
    float v1 = x[((size_t)b * 3 + 1) * NP + n];
    float v2 = x[((size_t)b * 3 + 2) * NP + n];
    float y0 = v0 * T[0] + v1 * T[3] + v2 * T[6];
    float y1 = v0 * T[1] + v1 * T[4] + v2 * T[7];
    float y2 = v0 * T[2] + v1 * T[5] + v2 * T[8];
    float* o = &xT[((size_t)b * NP + n) * 3];
    o[0] = y0; o[1] = y1; o[2] = y2;
    xx[b * NP + n] = y0 * y0 + y1 * y1 + y2 * y2;
    float* out = PQ + ((size_t)b * NP + n) * 128;
    for (int oo = 0; oo < 128; oo++)
        out[oo] = sw[oo * 3] * y0 + sw[oo * 3 + 1] * y1 + sw[oo * 3 + 2] * y2;
}

// ------------------------- kNN selection (REDUX argmax + top-4 cache) -------
__device__ __forceinline__ unsigned f2u(float f) {
    unsigned u = __float_as_uint(f);
    return (f >= 0.f) ? (u | 0x80000000u) : ~u;
}

struct Top4 { float v0, v1, v2, v3; int i0, i1, i2, i3; };

__device__ __forceinline__ void lane_top4(const float* dr, int lane, Top4& t) {
    t.v0 = t.v1 = t.v2 = t.v3 = -FLT_MAX;
    t.i0 = t.i1 = t.i2 = t.i3 = 0x7fffffff;
#pragma unroll 4
    for (int s = 0; s < NP / 32; s++) {
        int j = lane + (s << 5);
        float val = dr[j];
        if (val > t.v3) {
            if (val > t.v2) {
                if (val > t.v1) {
                    if (val > t.v0) {
                        t.v3 = t.v2; t.i3 = t.i2; t.v2 = t.v1; t.i2 = t.i1;
                        t.v1 = t.v0; t.i1 = t.i0; t.v0 = val; t.i0 = j;
                    } else {
                        t.v3 = t.v2; t.i3 = t.i2; t.v2 = t.v1; t.i2 = t.i1;
                        t.v1 = val; t.i1 = j;
                    }
                } else { t.v3 = t.v2; t.i3 = t.i2; t.v2 = val; t.i2 = j; }
            } else { t.v3 = val; t.i3 = j; }
        }
    }
}

__device__ __forceinline__ void knn_select(float* dr, int* orow, int lane) {
    Top4 t;
    lane_top4(dr, lane, t);
    unsigned key = f2u(t.v0);
    for (int k = 0; k < KNB; k++) {
        unsigned bk = __reduce_max_sync(~0u, key);
        unsigned winners = __ballot_sync(~0u, key == bk);
        int wl = __ffs(winners) - 1;
        int bi = __shfl_sync(~0u, t.i0, wl);
        if (lane == 0) orow[k] = bi;
        if (lane == wl) {
            dr[t.i0] = -FLT_MAX;
            t.v0 = t.v1; t.i0 = t.i1;
            t.v1 = t.v2; t.i1 = t.i2;
            t.v2 = t.v3; t.i2 = t.i3;
            t.v3 = -FLT_MAX; t.i3 = 0x7fffffff;
            if (t.v0 == -FLT_MAX) lane_top4(dr, lane, t);
            key = f2u(t.v0);
        }
    }
}

__global__ void knn3_kernel(const float* __restrict__ xT, const float* __restrict__ xx,
                            int* __restrict__ idx) {
    extern __shared__ float dist[];  // 8 * NP
    __shared__ float sctr[8][3];
    const int b = blockIdx.y, r0 = blockIdx.x * 8, tid = threadIdx.x;

    for (int e = tid; e < 24; e += 256)
        sctr[e / 3][e % 3] = xT[((size_t)b * NP + r0 + e / 3) * 3 + e % 3];
    __syncthreads();

    for (int j = tid; j < NP; j += 256) {
        const float* pj = xT + ((size_t)b * NP + j) * 3;
        float w0 = pj[0], w1 = pj[1], w2 = pj[2];
        float xxj = xx[b * NP + j];
#pragma unroll
        for (int r = 0; r < 8; r++) {
            float a = w0 * sctr[r][0] + w1 * sctr[r][1] + w2 * sctr[r][2];
            dist[r * NP + j] = 2.f * a - xxj;
        }
    }
    __syncthreads();

    const int w = tid >> 5, lane = tid & 31;
    knn_select(dist + w * NP, idx + ((size_t)b * NP + r0 + w) * KNB, lane);
}

// C=64 kNN: 8 rows/block, 256 threads, j-vectorized (float4) distance phase
__global__ void knnC_kernel(const float* __restrict__ xC, int* __restrict__ idx) {
    extern __shared__ float dist[];  // 8 * NP
    __shared__ float sctr[8][64];
    const int b = blockIdx.y, r0 = blockIdx.x * 8, tid = threadIdx.x;

    for (int e = tid; e < 8 * 64; e += 256) {
        int r = e / 64, c = e % 64;
        sctr[r][c] = xC[((size_t)b * 64 + c) * NP + r0 + r];
    }
    __syncthreads();

    for (int j4 = tid * 4; j4 < NP; j4 += 1024) {
        float4 acc[8];
#pragma unroll
        for (int r = 0; r < 8; r++) acc[r] = make_float4(0.f, 0.f, 0.f, 0.f);
        float4 sq = make_float4(0.f, 0.f, 0.f, 0.f);
        for (int c = 0; c < 64; c++) {
            float4 v = *(const float4*)&xC[((size_t)b * 64 + c) * NP + j4];
            sq.x += v.x * v.x; sq.y += v.y * v.y; sq.z += v.z * v.z; sq.w += v.w * v.w;
#pragma unroll
            for (int r = 0; r < 8; r++) {
                float s = sctr[r][c];
                acc[r].x += v.x * s; acc[r].y += v.y * s;
                acc[r].z += v.z * s; acc[r].w += v.w * s;
            }
        }
#pragma unroll
        for (int r = 0; r < 8; r++) {
            float4 dv;
            dv.x = 2.f * acc[r].x - sq.x;
            dv.y = 2.f * acc[r].y - sq.y;
            dv.z = 2.f * acc[r].z - sq.z;
            dv.w = 2.f * acc[r].w - sq.w;
            *(float4*)&dist[r * NP + j4] = dv;
        }
    }
    __syncthreads();

    const int w = tid >> 5, lane = tid & 31;
    knn_select(dist + w * NP, idx + ((size_t)b * NP + r0 + w) * KNB, lane);
}

// --------- edge layer-2 (R15 proven: transposed sH, 8x4 tiles, kt=r/OT) -----
// h[k] = lrelu(P[idx[k]] + Q[n]); out = max_k lrelu(h @ W2)
template <int COUT, int P>
__global__ __launch_bounds__(320) void edge2_kernel(
        const float* __restrict__ PQ, const int* __restrict__ idx,
        const float* __restrict__ W2T,  // [64][COUT]
        float* __restrict__ out, int old, int ooff, float* __restrict__ outC) {
    constexpr int NT = 320;
    constexpr int KT = KNB / 8;           // 5
    constexpr int OT = COUT / 4;
    constexpr int TPP = KT * OT;
    static_assert(P * TPP == NT, "tile/thread mismatch");
    constexpr int PK = P * KNB;           // 80 or 160 (multiple of 4)
    extern __shared__ float sm[];
    float* sW2 = sm;                      // 64*COUT
    float* sHT = sW2 + 64 * COUT;         // [64][PK]  (c-major, k contiguous)
    float* sP  = sHT + 64 * PK;           // P*KT*COUT partial maxes
    __shared__ float sQ[P][64];
    __shared__ int sidx[P * KNB];

    const int b = blockIdx.y, n0 = blockIdx.x * P, tid = threadIdx.x;

    for (int e = tid; e < 64 * COUT; e += NT) sW2[e] = W2T[e];
    for (int e = tid; e < P * KNB; e += NT)
        sidx[e] = idx[((size_t)b * NP + n0 + e / KNB) * KNB + e % KNB];
    for (int e = tid; e < P * 64; e += NT)
        sQ[e >> 6][e & 63] = PQ[((size_t)b * NP + n0 + (e >> 6)) * 128 + 64 + (e & 63)];
    __syncthreads();

    // gather + transpose
    for (int e = tid; e < PK * 16; e += NT) {
        int pk = e % PK, c4 = e / PK;
        int p = pk / KNB;
        float4 v = *(const float4*)(PQ + ((size_t)b * NP + sidx[pk]) * 128 + c4 * 4);
        const float* q = &sQ[p][c4 * 4];
        sHT[(c4 * 4 + 0) * PK + pk] = lrelu(v.x + q[0]);
        sHT[(c4 * 4 + 1) * PK + pk] = lrelu(v.y + q[1]);
        sHT[(c4 * 4 + 2) * PK + pk] = lrelu(v.z + q[2]);
        sHT[(c4 * 4 + 3) * PK + pk] = lrelu(v.w + q[3]);
    }
    __syncthreads();

    {
        int p = tid / TPP, r = tid % TPP, kt = r / OT, ot = r % OT;
        const float* Abase = sHT + p * KNB + kt * 8;   // + c*PK per step
        const float* W = sW2 + ot * 4;
        float acc[8][4] = {};
        for (int c = 0; c < 64; c++) {
            float4 A0 = *(const float4*)(Abase + c * PK);
            float4 A1 = *(const float4*)(Abase + c * PK + 4);
            float4 w = *(const float4*)(W + c * COUT);
            float a[8] = {A0.x, A0.y, A0.z, A0.w, A1.x, A1.y, A1.z, A1.w};
#pragma unroll
            for (int i = 0; i < 8; i++) {
                acc[i][0] += a[i] * w.x; acc[i][1] += a[i] * w.y;
                acc[i][2] += a[i] * w.z; acc[i][3] += a[i] * w.w;
            }
        }
        // fused max over the 8 k-rows of this tile
        float* d = sP + ((size_t)p * KT + kt) * COUT + ot * 4;
#pragma unroll
        for (int oi = 0; oi < 4; oi++) {
            float m = lrelu(acc[0][oi]);
#pragma unroll
            for (int i = 1; i < 8; i++) m = fmaxf(m, lrelu(acc[i][oi]));
            d[oi] = m;
        }
    }
    __syncthreads();

    for (int o = tid; o < P * COUT; o += NT) {
        int p = o / COUT, oo = o % COUT;
        const float* col = sP + (size_t)p * KT * COUT + oo;
        float m = col[0];
#pragma unroll
        for (int kt = 1; kt < KT; kt++) m = fmaxf(m, col[kt * COUT]);
        int n = n0 + p;
        out[((size_t)b * NP + n) * old + ooff + oo] = m;
        if (outC) outC[((size_t)b * 64 + oo) * NP + n] = m;
    }
}

// E4: out[n,o] = lrelu(max_k P[idx[n,k],o] + Q[n,o])
__global__ void gathermax_kernel(const float* __restrict__ PQ, const int* __restrict__ idx,
                                 float* __restrict__ out, int old, int ooff) {
    __shared__ int sidx[2][KNB];
    int b = blockIdx.y, tid = threadIdx.x;
    int p = tid >> 6, oo = tid & 63;
    int n = blockIdx.x * 2 + p;
    if (tid < 2 * KNB)
        sidx[tid / KNB][tid % KNB] = idx[((size_t)b * NP + blockIdx.x * 2 + tid / KNB) * KNB + tid % KNB];
    __syncthreads();
    float m = -FLT_MAX;
#pragma unroll 4
    for (int k = 0; k < KNB; k++)
        m = fmaxf(m, PQ[((size_t)b * NP + sidx[p][k]) * 128 + oo]);
    float q = PQ[((size_t)b * NP + n) * 128 + 64 + oo];
    out[((size_t)b * NP + n) * old + ooff + oo] = lrelu(m + q);
}

// ------------------------- 128x128-tile pointwise conv (8x8 microtile) ------
__global__ __launch_bounds__(256) void pconv128_kernel(
        const float* __restrict__ in, int ld, int coff,
        const float* __restrict__ WT, int CIN, int OCP,
        const float* __restrict__ bias, int bstride,
        float* __restrict__ out, int old, int ooff, int act,
        float* __restrict__ pmax) {
    __shared__ float sA[16][132];
    __shared__ float sB[16][128];
    __shared__ float sR[16][128];
    const int b = blockIdx.z;
    const int n0 = blockIdx.x * 128, o0 = blockIdx.y * 128;
    const int tid = threadIdx.x;
    const int tx = tid & 15, ty = tid >> 4;
    float acc[8][8] = {};

    for (int c0 = 0; c0 < CIN; c0 += 16) {
        {
            int n = tid >> 1;
            int cbase = (tid & 1) * 4;
            const float* src = in + ((size_t)b * NP + n0 + n) * ld + coff + c0;
#pragma unroll
            for (int p = 0; p < 2; p++) {
                float4 v = *(const float4*)(src + cbase + p * 8);
                sA[cbase + p * 8 + 0][n] = v.x; sA[cbase + p * 8 + 1][n] = v.y;
                sA[cbase + p * 8 + 2][n] = v.z; sA[cbase + p * 8 + 3][n] = v.w;
            }
        }
        {
            int c = tid >> 5, o4 = (tid & 31) * 4;
#pragma unroll
            for (int p = 0; p < 2; p++)
                *(float4*)&sB[c + p * 8][o4] =
                    *(const float4*)(WT + (size_t)(c0 + c + p * 8) * OCP + o0 + o4);
        }
        __syncthreads();
#pragma unroll
        for (int c = 0; c < 16; c++) {
            float4 a0 = *(const float4*)&sA[c][ty * 8];
            float4 a1 = *(const float4*)&sA[c][ty * 8 + 4];
            float4 b0 = *(const float4*)&sB[c][tx * 8];
            float4 b1 = *(const float4*)&sB[c][tx * 8 + 4];
            float av[8] = {a0.x, a0.y, a0.z, a0.w, a1.x, a1.y, a1.z, a1.w};
            float bv[8] = {b0.x, b0.y, b0.z, b0.w, b1.x, b1.y, b1.z, b1.w};
#pragma unroll
            for (int i = 0; i < 8; i++)
#pragma unroll
                for (int j = 0; j < 8; j++) acc[i][j] += av[i] * bv[j];
        }
        __syncthreads();
    }

    if (pmax) {  // act=1 assumed; per-block partial max over 128 n's
#pragma unroll
        for (int j = 0; j < 8; j++) {
            float m = lrelu(acc[0][j]);
#pragma unroll
            for (int i = 1; i < 8; i++) m = fmaxf(m, lrelu(acc[i][j]));
            sR[ty][tx * 8 + j] = m;
        }
        __syncthreads();
        if (tid < 128) {
            float m = sR[0][tid];
#pragma unroll
            for (int r = 1; r < 16; r++) m = fmaxf(m, sR[r][tid]);
            pmax[((size_t)blockIdx.x * BN + b) * 1024 + o0 + tid] = m;
        }
        return;
    }

    float bvv[8];
    if (bias) {
#pragma unroll
        for (int j = 0; j < 8; j++) bvv[j] = bias[b * bstride + o0 + tx * 8 + j];
    }
#pragma unroll
    for (int i = 0; i < 8; i++) {
        int n = n0 + ty * 8 + i;
        float vals[8];
#pragma unroll
        for (int j = 0; j < 8; j++) {
            float v = acc[i][j];
            if (bias) v += bvv[j];
            if (act) v = lrelu(v);
            vals[j] = v;
        }
        float* dst = out + ((size_t)b * NP + n) * old + ooff + o0 + tx * 8;
        *(float4*)dst = make_float4(vals[0], vals[1], vals[2], vals[3]);
        *(float4*)(dst + 4) = make_float4(vals[4], vals[5], vals[6], vals[7]);
    }
}

// ------------------------- small-OC pointwise conv (final layer) ------------
__global__ void pconv_kernel(const float* __restrict__ in, int ld, int coff,
                             const float* __restrict__ WT, int CIN, int OCP,
                             float* __restrict__ out, int OC) {
    __shared__ float sA[16][68];
    __shared__ float sB[16][64];
    const int b = blockIdx.z;
    const int n0 = blockIdx.x * 64, o0 = blockIdx.y * 64;
    const int tid = threadIdx.x;
    const int tx = tid % 16, ty = tid / 16;
    float acc[4][4] = {};

    for (int c0 = 0; c0 < CIN; c0 += 16) {
        {
            int p = tid >> 2, c4 = (tid & 3) * 4;
            const float* src = in + ((size_t)b * NP + n0 + p) * ld + coff + c0 + c4;
            float4 v = *(const float4*)src;
            sA[c4 + 0][p] = v.x; sA[c4 + 1][p] = v.y;
            sA[c4 + 2][p] = v.z; sA[c4 + 3][p] = v.w;
        }
        {
            int c = tid >> 4, o4 = (tid & 15) * 4;
            *(float4*)&sB[c][o4] = *(const float4*)(WT + (size_t)(c0 + c) * OCP + o0 + o4);
        }
        __syncthreads();
#pragma unroll
        for (int c = 0; c < 16; c++) {
            float4 av = *(const float4*)&sA[c][ty * 4];
            float4 bv = *(const float4*)&sB[c][tx * 4];
            acc[0][0]+=av.x*bv.x; acc[0][1]+=av.x*bv.y; acc[0][2]+=av.x*bv.z; acc[0][3]+=av.x*bv.w;
            acc[1][0]+=av.y*bv.x; acc[1][1]+=av.y*bv.y; acc[1][2]+=av.y*bv.z; acc[1][3]+=av.y*bv.w;
            acc[2][0]+=av.z*bv.x; acc[2][1]+=av.z*bv.y; acc[2][2]+=av.z*bv.z; acc[2][3]+=av.z*bv.w;
            acc[3][0]+=av.w*bv.x; acc[3][1]+=av.w*bv.y; acc[3][2]+=av.w*bv.z; acc[3][3]+=av.w*bv.w;
        }
        __syncthreads();
    }

#pragma unroll
    for (int i = 0; i < 4; i++) {
        int n = n0 + ty * 4 + i;
#pragma unroll
        for (int j = 0; j < 4; j++) {
            int o = o0 + tx * 4 + j;
            if (o >= OC) continue;
            out[((size_t)b * OC + o) * NP + n] = acc[i][j];  // column-major final output
        }
    }
}

__global__ void pmaxreduce_kernel(const float* __restrict__ pm, float* __restrict__ out,
                                  int ostride, int ooff, int nblk) {
    int gid = blockIdx.x * blockDim.x + threadIdx.x;
    if (gid >= BN * 1024) return;
    int b = gid / 1024, o = gid % 1024;
    float m = -FLT_MAX;
    for (int blk = 0; blk < nblk; blk++)
        m = fmaxf(m, pm[((size_t)blk * BN + b) * 1024 + o]);
    out[(size_t)b * ostride + ooff + o] = m;
}

__global__ void fc_kernel(const float* __restrict__ in, int istride, int C,
                          const float* __restrict__ W, int wld, int O,
                          const float* __restrict__ bias, int bstride,
                          float* __restrict__ out, int ostride, int ooff, int act) {
    int b = blockIdx.x;
    int o = blockIdx.y * blockDim.x + threadIdx.x;
    if (o >= O) return;
    const float* ip = in + (size_t)b * istride;
    const float* wp = W + (size_t)o * wld;
    float s = 0.f;
    for (int c = 0; c < C; c++) s += ip[c] * wp[c];
    if (bias) s += bias[(size_t)b * bstride + o];
    if (act) s = lrelu(s);
    out[(size_t)b * ostride + ooff + o] = s;
}

// ------------------------- host -------------------------
extern "C" void kernel_launch(void* const* d_in, const int* in_sizes, int n_in,
                              void* d_out, int out_size) {
    const float* x    = (const float*)d_in[0];
    const float* l    = (const float*)d_in[1];
    const float* t_c1 = (const float*)d_in[2];
    const float* t_c2 = (const float*)d_in[3];
    const float* t_c3 = (const float*)d_in[4];
    const float* t_f1 = (const float*)d_in[5];
    const float* t_f2 = (const float*)d_in[6];
    const float* t_f3w= (const float*)d_in[7];
    const float* t_f3b= (const float*)d_in[8];
    const float* b1a  = (const float*)d_in[9];
    const float* b1b  = (const float*)d_in[10];
    const float* b2a  = (const float*)d_in[11];
    const float* b2b  = (const float*)d_in[12];
    const float* b3a  = (const float*)d_in[13];
    const float* m1   = (const float*)d_in[14];
    const float* m2   = (const float*)d_in[15];
    const float* h1   = (const float*)d_in[16];
    const float* h2   = (const float*)d_in[17];
    const float* h3   = (const float*)d_in[18];
    const float* h4   = (const float*)d_in[19];

    float *xTa, *xTb, *xx, *t128, *PQ, *xC, *pm, *cat, *vec, *t1024, *t512, *t256, *T9, *bsb, *hA, *hB, *WT;
    int* idxp;
    cudaGetSymbolAddress((void**)&xTa, g_xTa);
    cudaGetSymbolAddress((void**)&xTb, g_xTb);
    cudaGetSymbolAddress((void**)&xx, g_xx);
    cudaGetSymbolAddress((void**)&idxp, g_idx);
    cudaGetSymbolAddress((void**)&t128, g_t128);
    cudaGetSymbolAddress((void**)&PQ, g_PQ);
    cudaGetSymbolAddress((void**)&xC, g_xC);
    cudaGetSymbolAddress((void**)&pm, g_pm);
    cudaGetSymbolAddress((void**)&cat, g_cat);
    cudaGetSymbolAddress((void**)&vec, g_vec);
    cudaGetSymbolAddress((void**)&t1024, g_t1024);
    cudaGetSymbolAddress((void**)&t512, g_t512);
    cudaGetSymbolAddress((void**)&t256, g_t256);
    cudaGetSymbolAddress((void**)&T9, g_T9);
    cudaGetSymbolAddress((void**)&bsb, g_bias);
    cudaGetSymbolAddress((void**)&hA, g_hA);
    cudaGetSymbolAddress((void**)&hB, g_hB);
    cudaGetSymbolAddress((void**)&WT, g_WT);

    const int KNN_SMEM = 8 * NP * 4;                                    // 65536
    const int E128 = (64*128 + 64*(2*KNB) + 2*(KNB/8)*128) * 4;         // 58368
    const int E64  = (64*64  + 64*(4*KNB) + 4*(KNB/8)*64) * 4;          // 62464
    cudaFuncSetAttribute(knn3_kernel, cudaFuncAttributeMaxDynamicSharedMemorySize, KNN_SMEM);
    cudaFuncSetAttribute(knnC_kernel, cudaFuncAttributeMaxDynamicSharedMemorySize, KNN_SMEM);
    cudaFuncSetAttribute((const void*)edge2_kernel<128,2>, cudaFuncAttributeMaxDynamicSharedMemorySize, E128);
    cudaFuncSetAttribute((const void*)edge2_kernel<64,4>,  cudaFuncAttributeMaxDynamicSharedMemorySize, E64);

    // ---- front ordered so launch index 3 (profiled) = edge2<128,2> ----
    prep_pq_kernel<<<dim3(NP / 256, BN), 256>>>(x, t_c1, xTa, xx, PQ);                  // 0
    tw_kernel<<<(64*128 + 255) / 256, 256>>>(t_c2, 128, 64, 64, 0, WT + OFF_tc2, 128);  // 1
    knn3_kernel<<<dim3(NP / 8, BN), 256, KNN_SMEM>>>(xTa, xx, idxp);                    // 2
    edge2_kernel<128,2><<<dim3(NP / 2, BN), 320, E128>>>(PQ, idxp, WT + OFF_tc2,
                                                         t128, 128, 0, nullptr);        // 3 (profiled)

    // ---- remaining weight prep: ONE batched launch ----
    {
        TWTab t = {};
        struct S { const float* W; int C, ldW, coff, OCP, O, dstOff, mode; };
        S segs[] = {
            {t_c3, 128, 128, 0, 1024, 1024, OFF_tc3, 0},
            {b1b, 64, 64, 0, 64, 64, OFF_b1b, 0},
            {b2b, 64, 64, 0, 64, 64, OFF_b2b, 0},
            {m1, 192, 192, 0, 1024, 1024, OFF_m1, 0},
            {h1, 192, 1280, 1088, 256, 256, OFF_h1p, 0},
            {h2, 256, 256, 0, 256, 256, OFF_h2, 0},
            {h3, 256, 256, 0, 128, 128, OFF_h3, 0},
            {h4, 128, 128, 0, 64, 50, OFF_h4, 0},
            {b2a, 64, 128, 0, 128, 0, OFF_pq2, 1},
            {b3a, 64, 128, 0, 128, 0, OFF_pq3, 1},
        };
        int acc = 0;
        t.nseg = 10;
        for (int s = 0; s < 10; s++) {
            t.W[s] = segs[s].W; t.C[s] = segs[s].C; t.ldW[s] = segs[s].ldW;
            t.coff[s] = segs[s].coff; t.OCP[s] = segs[s].OCP; t.O[s] = segs[s].O;
            t.dstOff[s] = segs[s].dstOff; t.mode[s] = segs[s].mode;
            acc += segs[s].C * segs[s].OCP;
            t.end[s] = acc;
        }
        twall_kernel<<<(acc + 255) / 256, 256>>>(t, WT);
    }

    // ---- transform net (cont.) ----
    pconv128_kernel<<<dim3(16, 8, BN), 256>>>(t128, 128, 0, WT + OFF_tc3, 128, 1024,
                                              nullptr, 0, nullptr, 0, 0, 1, pm);
    pmaxreduce_kernel<<<(BN * 1024 + 255) / 256, 256>>>(pm, t1024, 1024, 0, 16);
    fc_kernel<<<dim3(BN, 2), 256>>>(t1024, 1024, 1024, t_f1, 1024, 512, nullptr, 0, t512, 512, 0, 1);
    fc_kernel<<<dim3(BN, 1), 256>>>(t512, 512, 512, t_f2, 512, 256, nullptr, 0, t256, 256, 0, 1);
    fc_kernel<<<dim3(BN, 1), 256>>>(t256, 256, 256, t_f3w, 256, 9, t_f3b, 0, T9, 9, 0, 0);
    transform_pq_kernel<<<dim3(NP / 256, BN), 256>>>(x, T9, b1a, xTb, xx, PQ);

    // ---- edge block 1 ----
    knn3_kernel<<<dim3(NP / 8, BN), 256, KNN_SMEM>>>(xTb, xx, idxp);
    edge2_kernel<64,4><<<dim3(NP / 4, BN), 320, E64>>>(PQ, idxp, WT + OFF_b1b, cat, 192, 0, xC);

    // ---- edge block 2 ----
    knnC_kernel<<<dim3(NP / 8, BN), 256, KNN_SMEM>>>(xC, idxp);
    pconv128_kernel<<<dim3(16, 1, BN), 256>>>(cat, 192, 0, WT + OFF_pq2, 64, 128,
                                              nullptr, 0, PQ, 128, 0, 0, nullptr);
    edge2_kernel<64,4><<<dim3(NP / 4, BN), 320, E64>>>(PQ, idxp, WT + OFF_b2b, cat, 192, 64, xC);

    // ---- edge block 3 (collapsed) ----
    knnC_kernel<<<dim3(NP / 8, BN), 256, KNN_SMEM>>>(xC, idxp);
    pconv128_kernel<<<dim3(16, 1, BN), 256>>>(cat, 192, 64, WT + OFF_pq3, 64, 128,
                                              nullptr, 0, PQ, 128, 0, 0, nullptr);
    gathermax_kernel<<<dim3(NP / 2, BN), 128>>>(PQ, idxp, cat, 192, 128);

    // ---- global features ----
    pconv128_kernel<<<dim3(16, 8, BN), 256>>>(cat, 192, 0, WT + OFF_m1, 192, 1024,
                                              nullptr, 0, nullptr, 0, 0, 1, pm);
    pmaxreduce_kernel<<<(BN * 1024 + 255) / 256, 256>>>(pm, vec, 1088, 0, 16);
    fc_kernel<<<dim3(BN, 1), 256>>>(l, 16, 16, m2, 16, 64, nullptr, 0, vec, 1088, 1024, 1);
    fc_kernel<<<dim3(BN, 1), 256>>>(vec, 1088, 1088, h1, 1280, 256, nullptr, 0, bsb, 256, 0, 0);

    // ---- head ----
    pconv128_kernel<<<dim3(16, 2, BN), 256>>>(cat, 192, 0, WT + OFF_h1p, 192, 256,
                                              bsb, 256, hA, 256, 0, 1, nullptr);
    pconv128_kernel<<<dim3(16, 2, BN), 256>>>(hA, 256, 0, WT + OFF_h2, 256, 256,
                                              nullptr, 0, hB, 256, 0, 1, nullptr);
    pconv128_kernel<<<dim3(16, 1, BN), 256>>>(hB, 256, 0, WT + OFF_h3, 256, 128,
                                              nullptr, 0, hA, 128, 0, 1, nullptr);
    pconv_kernel<<<dim3(32, 1, BN), 256>>>(hA, 128, 0, WT + OFF_h4, 128, 64,
                                           (float*)d_out, 50);
}